// round 1
// baseline (speedup 1.0000x reference)
#include <cuda_runtime.h>
#include <cstdint>

#define BB 1024
#define TT 1024
#define HH 50
#define GG 200
#define PP 16

// fast, accurate-enough activations (error ~1e-7, safe at +-inf)
__device__ __forceinline__ float sigmoid_fast(float v) {
    float e = __expf(-v);
    return __fdividef(1.0f, 1.0f + e);
}
__device__ __forceinline__ float tanh_fast(float v) {
    float e = __expf(2.0f * v);
    return 1.0f - __fdividef(2.0f, e + 1.0f);
}

__device__ __forceinline__ uint64_t pack2(float lo, float hi) {
    uint64_t r;
    asm("mov.b64 %0, {%1, %2};" : "=l"(r) : "f"(lo), "f"(hi));
    return r;
}
__device__ __forceinline__ void unpack2(uint64_t v, float& lo, float& hi) {
    asm("mov.b64 {%0, %1}, %2;" : "=f"(lo), "=f"(hi) : "l"(v));
}
__device__ __forceinline__ void fma2(uint64_t& acc, uint64_t a, uint64_t b) {
    asm("fma.rn.f32x2 %0, %1, %2, %0;" : "+l"(acc) : "l"(a), "l"(b));
}

__global__ __launch_bounds__(256, 3)
void lstm_fused_kernel(const float* __restrict__ x,
                       const float* __restrict__ params,
                       const float* __restrict__ W_ih,
                       const float* __restrict__ W_hh,
                       const float* __restrict__ b_ih,
                       const float* __restrict__ b_hh,
                       const float* __restrict__ W_lin,
                       const float* __restrict__ b_lin,
                       float* __restrict__ out)
{
    __shared__ __align__(16) float xs[TT];        // this batch's input row
    __shared__ __align__(16) float hh[32][52];    // h history ring (52-float stride, 16B rows)
    __shared__ float wlin[72];                    // W_lin padded

    const int tid = threadIdx.x;
    const int b   = blockIdx.x;
    const int lane = tid & 31;

    // ---- init: stage x row, W_lin, zero h[-1] ----
    {
        const float4* x4 = reinterpret_cast<const float4*>(x + (size_t)b * TT);
        reinterpret_cast<float4*>(xs)[tid] = x4[tid];   // 256 * 4 = 1024
        if (tid < 72) wlin[tid] = (tid < HH + PP) ? W_lin[tid] : 0.0f;
        if (tid < 52) hh[31][tid] = 0.0f;
    }
    const float blin = b_lin[0];

    // ---- gate-thread setup: thread 4j+k owns gate row r = k*50+j ----
    // threads [200,224) do dummy gate work (full warp 6) so shfl masks stay full
    const bool gate_thread = (tid < 224);
    const bool real_gate   = (tid < GG);
    const int  j = tid >> 2;
    const int  k = tid & 3;
    const int  r = k * HH + min(j, HH - 1);

    float wih = 0.0f, bias = 0.0f;
    uint64_t w2[25];
    if (gate_thread) {
        wih  = W_ih[r];
        bias = b_ih[r] + b_hh[r];
        const float2* wr = reinterpret_cast<const float2*>(W_hh + r * HH);  // 8B aligned (200*r)
        #pragma unroll
        for (int q = 0; q < 25; ++q) {
            float2 v = wr[q];
            w2[q] = pack2(v.x, v.y);
        }
    }
    __syncthreads();

    float c = 0.0f;   // leader (k==0) cell state

    #pragma unroll 1
    for (int t = 0; t < TT; ++t) {
        const int cur  = t & 31;
        const int prev = (t + 31) & 31;

        if (gate_thread) {
            const float xt = xs[t];
            const float g0 = fmaf(xt, wih, bias);
            uint64_t acc0 = pack2(g0, 0.0f);
            uint64_t acc1 = 0ull;

            const uint64_t*   hp  = reinterpret_cast<const uint64_t*>(&hh[prev][0]);
            const ulonglong2* hp2 = reinterpret_cast<const ulonglong2*>(hp);
            #pragma unroll
            for (int q2 = 0; q2 < 12; ++q2) {          // pairs 0..23 (floats 0..47)
                ulonglong2 hv = hp2[q2];                // LDS.128
                fma2(acc0, w2[2 * q2],     hv.x);
                fma2(acc1, w2[2 * q2 + 1], hv.y);
            }
            fma2(acc0, w2[24], hp[24]);                 // floats 48,49

            float a_lo, a_hi, c_lo, c_hi;
            unpack2(acc0, a_lo, a_hi);
            unpack2(acc1, c_lo, c_hi);
            const float gate = (a_lo + a_hi) + (c_lo + c_hi);

            // gate order: k=0 i, k=1 f, k=2 g(tanh), k=3 o
            const float val = (k == 2) ? tanh_fast(gate) : sigmoid_fast(gate);

            const int qb = lane & ~3;
            const float vf = __shfl_sync(0xffffffffu, val, qb | 1);
            const float vg = __shfl_sync(0xffffffffu, val, qb | 2);
            const float vo = __shfl_sync(0xffffffffu, val, qb | 3);

            if (k == 0) {
                c = fmaf(vf, c, val * vg);              // sig(f)*c + sig(i)*tanh(g)
                const float hnew = vo * tanh_fast(c);
                if (real_gate) hh[cur][j] = hnew;
            }
        }

        // ---- bulk output flush every 32 steps ----
        if ((t & 31) == 31) {
            __syncthreads();                            // h writes -> flush reads
            const int ttl  = tid >> 3;                  // timestep slot 0..31
            const int part = tid & 7;
            const int tg   = t - 31 + ttl;              // row index == ttl
            float s = 0.0f;
            const float* prow = params + ((size_t)b * TT + tg) * PP - HH;
            #pragma unroll
            for (int jj = part; jj < HH + PP; jj += 8) {
                const float v = (jj < HH) ? hh[ttl][jj] : __ldg(prow + jj);
                s = fmaf(wlin[jj], v, s);
            }
            s += __shfl_down_sync(0xffffffffu, s, 4, 8);
            s += __shfl_down_sync(0xffffffffu, s, 2, 8);
            s += __shfl_down_sync(0xffffffffu, s, 1, 8);
            if (part == 0) out[(size_t)b * TT + tg] = s + blin;
        }

        __syncthreads();                                // step barrier (h RAW + ring reuse)
    }
}

extern "C" void kernel_launch(void* const* d_in, const int* in_sizes, int n_in,
                              void* d_out, int out_size)
{
    const float* x      = (const float*)d_in[0];
    const float* params = (const float*)d_in[1];
    const float* W_ih   = (const float*)d_in[2];
    const float* W_hh   = (const float*)d_in[3];
    const float* b_ih   = (const float*)d_in[4];
    const float* b_hh   = (const float*)d_in[5];
    const float* W_lin  = (const float*)d_in[6];
    const float* b_lin  = (const float*)d_in[7];
    float* out = (float*)d_out;

    lstm_fused_kernel<<<BB, 256>>>(x, params, W_ih, W_hh, b_ih, b_hh,
                                   W_lin, b_lin, out);
}